// round 10
// baseline (speedup 1.0000x reference)
#include <cuda_runtime.h>
#include <cuda_fp16.h>
#include <cstdint>

// ============================================================================
// GGRUCell on GB300 — HMMA fp16 single-term GEMMs.
// R10: occupancy play. Warp tile 32x32 (acc=32 regs), CTA 128x64,
// __launch_bounds__(256,3) -> 3 CTAs/SM = 24 warps (was 16). The R9 analysis
// showed HMMA rt~2cyc/SMSP with tensor at 39% and issue 21%: latency-bound,
// warp-starved. More resident warps is the lever.
//
//   R   = sigmoid(prev @ Wr + inp[:,2H:]) * inp[:,:H]
//   out = mask * (tanh(R @ U + inp[:,:H]) + 1) + prev   (update gate cancels)
// ============================================================================

#define HDIM   1024
#define BATCH  16384

static constexpr int M_TILE = 128;
static constexpr int N_TILE = 64;
static constexpr int KT     = 32;            // K-chunk
static constexpr int NC     = HDIM / 32;     // 32 k32-granules (B frag layout)
static constexpr int SA     = 40;            // padded smem row stride (fp16)
static constexpr int STAGES = 4;

static constexpr int A_BYTES     = 128 * SA * 2;          // 10240
static constexpr int B_BYTES     = 8 * 512;               // 8 n8-tiles x 512B
static constexpr int STG_BYTES   = A_BYTES + B_BYTES;     // 14336
static constexpr int OFF_B       = A_BYTES;
static constexpr int SMEM_BYTES  = STAGES * STG_BYTES;    // 57344

// --------------------------------------------------------------------------
__device__ __forceinline__ uint32_t smem_to_u32(const void* p) {
    uint32_t a;
    asm("{ .reg .u64 t; cvta.to.shared.u64 t, %1; cvt.u32.u64 %0, t; }" : "=r"(a) : "l"(p));
    return a;
}
#define CP_ASYNC16(s, g) \
    asm volatile("cp.async.cg.shared.global [%0], [%1], 16;" :: "r"(s), "l"(g) : "memory")
#define CP_COMMIT() asm volatile("cp.async.commit_group;" ::: "memory")
#define CP_WAIT2()  asm volatile("cp.async.wait_group 2;" ::: "memory")
#define CP_WAIT0()  asm volatile("cp.async.wait_group 0;" ::: "memory")

#define LDSM_X4(r0, r1, r2, r3, addr) \
    asm volatile("ldmatrix.sync.aligned.m8n8.x4.shared.b16 {%0,%1,%2,%3}, [%4];" \
                 : "=r"(r0), "=r"(r1), "=r"(r2), "=r"(r3) : "r"(addr))

#define LDS128(v, addr) \
    asm volatile("ld.shared.v4.u32 {%0,%1,%2,%3}, [%4];" \
                 : "=r"((v).x), "=r"((v).y), "=r"((v).z), "=r"((v).w) : "r"(addr))

#define MMA_F16_2(d, a, b0, b1) \
    asm volatile("mma.sync.aligned.m16n8k16.row.col.f32.f16.f16.f32 " \
                 "{%0,%1,%2,%3}, {%4,%5,%6,%7}, {%8,%9}, {%0,%1,%2,%3};" \
                 : "+f"((d)[0]), "+f"((d)[1]), "+f"((d)[2]), "+f"((d)[3]) \
                 : "r"((a)[0]), "r"((a)[1]), "r"((a)[2]), "r"((a)[3]), \
                   "r"(b0), "r"(b1))

// --------------------------------------------------------------------------
// Scratch (no cudaMalloc allowed)
// --------------------------------------------------------------------------
// B fragment-linear planes: index ((n8*NC + k32)*32 + lane) -> uint4 holding
// {b0,b1} for first k16 and {b0,b1} for second k16 of the k32 granule,
// per the m16n8k16 .col B layout (thread t: n=t/4, k=2*(t%4)+{0,1},+8,..).
__device__ uint4 g_W1f[(HDIM / 8) * NC * 32];
__device__ uint4 g_W2f[(HDIM / 8) * NC * 32];
__device__ __half g_Ph[(size_t)BATCH * HDIM];   // prev, fp16
__device__ __half g_Rh[(size_t)BATCH * HDIM];   // R = reset*state, fp16

__device__ __forceinline__ uint32_t pack_h2(__half a, __half b) {
    __half2 t; t.x = a; t.y = b;
    return *reinterpret_cast<uint32_t*>(&t);
}

// --------------------------------------------------------------------------
__global__ void wtrans_frag(const float* __restrict__ W, int ld, int off, int which) {
    const int t    = blockIdx.x * 256 + threadIdx.x;
    const int lane = t & 31;
    const int k32  = (t >> 5) & (NC - 1);
    const int n8   = t >> 10;
    const int n    = n8 * 8 + (lane >> 2);
    const int kb   = k32 * 32 + 2 * (lane & 3);
    uint32_t h[4];
#pragma unroll
    for (int w = 0; w < 4; w++) {
        const int k = kb + 8 * w;
        const float v0 = W[(size_t)k * ld + off + n];
        const float v1 = W[(size_t)(k + 1) * ld + off + n];
        h[w] = pack_h2(__float2half(v0), __float2half(v1));
    }
    uint4* F = which ? g_W2f : g_W1f;
    F[t] = make_uint4(h[0], h[1], h[2], h[3]);
}

// --------------------------------------------------------------------------
__global__ void psplit_kernel(const float* __restrict__ prev) {
    size_t i = ((size_t)blockIdx.x * 256 + threadIdx.x) * 4;
    float4 v = *reinterpret_cast<const float4*>(&prev[i]);
    uint32_t p01 = pack_h2(__float2half(v.x), __float2half(v.y));
    uint32_t p23 = pack_h2(__float2half(v.z), __float2half(v.w));
    *reinterpret_cast<uint2*>(&g_Ph[i]) = make_uint2(p01, p23);
}

// --------------------------------------------------------------------------
// GEMM: CTA 128x64, 8 warps (4M x 2N), warp tile 32x32, K-chunk 32,
// 4-stage cp.async pipeline, 3 CTAs/SM.
// --------------------------------------------------------------------------
template <bool FIRST>
__global__ void __launch_bounds__(256, 3)
gemm_kernel(const float* __restrict__ inp, const float* __restrict__ prev,
            const float* __restrict__ mask, float* __restrict__ out) {
    extern __shared__ char smem_raw[];
    const uint32_t sb = smem_to_u32(smem_raw);

    const int tid   = threadIdx.x;
    const int wid   = tid >> 5;
    const int lane  = tid & 31;
    const int warpM = wid >> 1;       // 4 warps over M (32 rows each)
    const int warpN = wid & 1;        // 2 warps over N (32 cols each)
    const int m0 = blockIdx.x * M_TILE;
    const int n0 = blockIdx.y * N_TILE;

    const __half* AHg = FIRST ? g_Ph : g_Rh;
    const uint4* __restrict__ BF = FIRST ? g_W1f : g_W2f;
    const int nb0 = n0 >> 3;          // CTA's base n8 tile (8 tiles)

    auto issue_chunk = [&](int kc, int stage) {
        const uint32_t s0 = sb + stage * STG_BYTES;
        // A: 128 rows x 4 granules (16B) = 512 granules, 2/thread
#pragma unroll
        for (int i = 0; i < 2; i++) {
            const int g   = tid + i * 256;
            const int row = g >> 2;
            const int ce  = (g & 3) * 8;
            const size_t gA = (size_t)(m0 + row) * HDIM + kc * KT + ce;
            const uint32_t so = (uint32_t)(row * SA + ce) * 2;
            CP_ASYNC16(s0 + so, AHg + gA);
        }
        // B: 8 n8-tiles x 32 lanes = 256 granules, 1/thread
        {
            const int t8 = tid >> 5;          // 0..7
            const int ln = tid & 31;
            const int idx = ((nb0 + t8) * NC + kc) * 32 + ln;
            CP_ASYNC16(s0 + OFF_B + (uint32_t)tid * 16, &BF[idx]);
        }
    };

    float acc[2][4][4];
#pragma unroll
    for (int i = 0; i < 2; i++)
#pragma unroll
        for (int j = 0; j < 4; j++)
#pragma unroll
            for (int k = 0; k < 4; k++) acc[i][j][k] = 0.f;

    issue_chunk(0, 0); CP_COMMIT();
    issue_chunk(1, 1); CP_COMMIT();
    issue_chunk(2, 2); CP_COMMIT();

    for (int c = 0; c < NC; c++) {
        if (c == NC - 1) { CP_WAIT0(); } else { CP_WAIT2(); }
        __syncthreads();
        if (c + 3 < NC) {
            issue_chunk(c + 3, (c + 3) & 3);
            CP_COMMIT();
        }

        const uint32_t s0 = sb + (c & 3) * STG_BYTES;
        const uint32_t sB = s0 + OFF_B + (uint32_t)warpN * 4 * 512 + lane * 16;

        // B fragments: 4 conflict-free LDS.128 (this warp's 4 n8 tiles)
        uint4 B4[4];
#pragma unroll
        for (int ni = 0; ni < 4; ni++) LDS128(B4[ni], sB + ni * 512);

#pragma unroll
        for (int kb2 = 0; kb2 < 2; kb2++) {
            const int kcol = kb2 * 16 + ((lane >> 4) << 3);
            uint32_t a0[4], a1[4];
            {
                const int r0 = warpM * 32 + (lane & 15);
                const int r1 = warpM * 32 + 16 + (lane & 15);
                const uint32_t o0 = (uint32_t)(r0 * SA + kcol) * 2;
                const uint32_t o1 = (uint32_t)(r1 * SA + kcol) * 2;
                LDSM_X4(a0[0], a0[1], a0[2], a0[3], s0 + o0);
                LDSM_X4(a1[0], a1[1], a1[2], a1[3], s0 + o1);
            }
#pragma unroll
            for (int ni = 0; ni < 4; ni++) {
                const uint32_t b0 = kb2 ? B4[ni].z : B4[ni].x;
                const uint32_t b1 = kb2 ? B4[ni].w : B4[ni].y;
                MMA_F16_2(acc[0][ni], a0, b0, b1);
                MMA_F16_2(acc[1][ni], a1, b0, b1);
            }
        }
    }

    // ---- epilogue ----
#pragma unroll
    for (int mi = 0; mi < 2; mi++) {
#pragma unroll
        for (int h = 0; h < 2; h++) {
            const int b = m0 + warpM * 32 + mi * 16 + h * 8 + (lane >> 2);
            float mval = 0.f;
            if (!FIRST) mval = __ldg(&mask[b]);
#pragma unroll
            for (int ni = 0; ni < 4; ni++) {
                const int n = n0 + warpN * 32 + ni * 8 + (lane & 3) * 2;
                const float v0 = acc[mi][ni][2 * h];
                const float v1 = acc[mi][ni][2 * h + 1];
                const float2 si = *reinterpret_cast<const float2*>(
                    &inp[(size_t)b * (3 * HDIM) + n]);
                if (FIRST) {
                    const float2 gi = *reinterpret_cast<const float2*>(
                        &inp[(size_t)b * (3 * HDIM) + 2 * HDIM + n]);
                    const float r0 = si.x / (1.f + __expf(-(v0 + gi.x)));
                    const float r1 = si.y / (1.f + __expf(-(v1 + gi.y)));
                    *reinterpret_cast<uint32_t*>(&g_Rh[(size_t)b * HDIM + n]) =
                        pack_h2(__float2half(r0), __float2half(r1));
                } else {
                    const float2 pv = *reinterpret_cast<const float2*>(
                        &prev[(size_t)b * HDIM + n]);
                    float2 o;
                    o.x = mval * (tanhf(v0 + si.x) + 1.f) + pv.x;
                    o.y = mval * (tanhf(v1 + si.y) + 1.f) + pv.y;
                    *reinterpret_cast<float2*>(&out[(size_t)b * HDIM + n]) = o;
                }
            }
        }
    }
}

// --------------------------------------------------------------------------
extern "C" void kernel_launch(void* const* d_in, const int* in_sizes, int n_in,
                              void* d_out, int out_size) {
    const float* inp  = (const float*)d_in[0];   // (B, 3H)
    const float* prev = (const float*)d_in[1];   // (B, H)
    const float* mask = (const float*)d_in[2];   // (B,)
    const float* Wur  = (const float*)d_in[3];   // (H, 2H)
    const float* U    = (const float*)d_in[4];   // (H, H)
    float* out = (float*)d_out;

    cudaFuncSetAttribute(gemm_kernel<true>,
                         cudaFuncAttributeMaxDynamicSharedMemorySize, SMEM_BYTES);
    cudaFuncSetAttribute(gemm_kernel<false>,
                         cudaFuncAttributeMaxDynamicSharedMemorySize, SMEM_BYTES);

    const int frag_slots = (HDIM / 8) * NC * 32;           // 131072
    wtrans_frag<<<frag_slots / 256, 256>>>(Wur, 2 * HDIM, HDIM, 0);  // Wr
    wtrans_frag<<<frag_slots / 256, 256>>>(U, HDIM, 0, 1);
    psplit_kernel<<<(BATCH * HDIM) / (256 * 4), 256>>>(prev);

    dim3 grid(BATCH / M_TILE, HDIM / N_TILE);
    gemm_kernel<true><<<grid, 256, SMEM_BYTES>>>(inp, prev, mask, out);
    gemm_kernel<false><<<grid, 256, SMEM_BYTES>>>(inp, prev, mask, out);
}